// round 13
// baseline (speedup 1.0000x reference)
#include <cuda_runtime.h>
#include <cuda_bf16.h>
#include <math.h>
#include <stdint.h>

#define NB    8192
#define DIM   128
#define NTOT  16384
#define INVT  14.285714285714286f

#define BM 128
#define BN 256
#define NT (NTOT/BN)              // 64 N-tiles per CTA

#define STRB 272                  // smem row stride in bytes (128 bf16 + 8 pad)
#define A_BYTES (128*STRB)        // 34816
#define B_BYTES (256*STRB)        // 69632 per buffer
#define SMEM_REQ (A_BYTES + 2*B_BYTES)   // 174080

__device__ __nv_bfloat16 g_repsb[(size_t)NTOT * DIM];   // 4 MB, L2-resident
__device__ float g_lse[NTOT];
__device__ float g_pos[NB];

// ---------------------------------------------------------------------------
__device__ __forceinline__ uint32_t smem_u32(const void* p) {
    uint32_t r;
    asm("{ .reg .u64 t; cvta.to.shared.u64 t, %1; cvt.u32.u64 %0, t; }" : "=r"(r) : "l"(p));
    return r;
}
__device__ __forceinline__ void cp16(uint32_t dst, const void* src) {
    asm volatile("cp.async.cg.shared.global [%0], [%1], 16;" :: "r"(dst), "l"(src));
}
__device__ __forceinline__ void cp_commit() { asm volatile("cp.async.commit_group;"); }
__device__ __forceinline__ void cp_wait0()  { asm volatile("cp.async.wait_group 0;"); }

__device__ __forceinline__ void ldsm4(uint32_t r[4], uint32_t addr) {
    asm volatile("ldmatrix.sync.aligned.m8n8.x4.shared.b16 {%0,%1,%2,%3}, [%4];"
        : "=r"(r[0]), "=r"(r[1]), "=r"(r[2]), "=r"(r[3]) : "r"(addr));
}
__device__ __forceinline__ void mma16816(float c[4], const uint32_t a[4],
                                         uint32_t b0, uint32_t b1) {
    asm volatile(
        "mma.sync.aligned.m16n8k16.row.col.f32.bf16.bf16.f32 "
        "{%0,%1,%2,%3}, {%4,%5,%6,%7}, {%8,%9}, {%0,%1,%2,%3};"
        : "+f"(c[0]), "+f"(c[1]), "+f"(c[2]), "+f"(c[3])
        : "r"(a[0]), "r"(a[1]), "r"(a[2]), "r"(a[3]), "r"(b0), "r"(b1));
}

// ---------------------------------------------------------------------------
// Normalize rows of [z_i; z_j] -> bf16(rn). One warp per row.
// ---------------------------------------------------------------------------
__global__ void nt_normalize(const float* __restrict__ zi,
                             const float* __restrict__ zj) {
    int row  = (blockIdx.x * blockDim.x + threadIdx.x) >> 5;
    int lane = threadIdx.x & 31;
    if (row >= NTOT) return;
    const float* src = (row < NB) ? (zi + (size_t)row * DIM)
                                  : (zj + (size_t)(row - NB) * DIM);
    float4 v = ((const float4*)src)[lane];
    float ss = v.x*v.x + v.y*v.y + v.z*v.z + v.w*v.w;
#pragma unroll
    for (int o = 16; o; o >>= 1) ss += __shfl_xor_sync(0xffffffffu, ss, o);
    float inv = 1.0f / fmaxf(sqrtf(ss), 1e-12f);
    __nv_bfloat162 p0, p1;
    p0.x = __float2bfloat16_rn(v.x*inv); p0.y = __float2bfloat16_rn(v.y*inv);
    p1.x = __float2bfloat16_rn(v.z*inv); p1.y = __float2bfloat16_rn(v.w*inv);
    __nv_bfloat162* dst = (__nv_bfloat162*)(g_repsb + (size_t)row * DIM);
    dst[lane*2]   = p0;
    dst[lane*2+1] = p1;
}

// ---------------------------------------------------------------------------
// pos[i] = exp(dot(zi_i/|zi_i|, zj_i/|zj_i|) / T)   (exact fp32 path)
// ---------------------------------------------------------------------------
__global__ void nt_pos(const float* __restrict__ zi,
                       const float* __restrict__ zj) {
    int row  = (blockIdx.x * blockDim.x + threadIdx.x) >> 5;
    int lane = threadIdx.x & 31;
    if (row >= NB) return;
    float4 a = ((const float4*)(zi + (size_t)row * DIM))[lane];
    float4 b = ((const float4*)(zj + (size_t)row * DIM))[lane];
    float sa = a.x*a.x + a.y*a.y + a.z*a.z + a.w*a.w;
    float sb = b.x*b.x + b.y*b.y + b.z*b.z + b.w*b.w;
    float d  = a.x*b.x + a.y*b.y + a.z*b.z + a.w*b.w;
#pragma unroll
    for (int o = 16; o; o >>= 1) {
        sa += __shfl_xor_sync(0xffffffffu, sa, o);
        sb += __shfl_xor_sync(0xffffffffu, sb, o);
        d  += __shfl_xor_sync(0xffffffffu, d,  o);
    }
    if (lane == 0) {
        float na = fmaxf(sqrtf(sa), 1e-12f);
        float nb = fmaxf(sqrtf(sb), 1e-12f);
        g_pos[row] = expf(d / (na * nb) * INVT);
    }
}

// ---------------------------------------------------------------------------
// Fused bf16 mma.sync GEMM + online double-logsumexp.
// CTA: 128 rows x 64 tiles of 256 cols. 8 warps = 2(M) x 4(N), warp tile 64x64.
// K=128 in one shot per tile (8 k16 steps); B tiles double-buffered (cp.async).
// ---------------------------------------------------------------------------
__global__ void __launch_bounds__(256, 1) nt_main() {
    extern __shared__ char smraw[];
    const uint32_t sA = smem_u32(smraw);
    const uint32_t sB = sA + A_BYTES;
    float* smf = (float*)smraw;

    const int tid   = threadIdx.x;
    const int lane  = tid & 31;
    const int wid   = tid >> 5;
    const int warpM = wid >> 2;       // 0..1
    const int warpN = wid & 3;        // 0..3
    const int mi    = lane >> 3;      // ldmatrix quadrant
    const int ri    = lane & 7;
    const int rt    = lane >> 2;      // C frag row
    const int qt    = lane & 3;       // C frag col pair
    const int r0    = blockIdx.x * BM;

    // ---- A block (128x128 bf16) -> smem
#pragma unroll
    for (int i = 0; i < 8; ++i) {
        int u = tid + i * 256;            // 0..2047
        int row = u >> 4, kq = u & 15;
        cp16(sA + (uint32_t)(row * STRB + kq * 16),
             g_repsb + (size_t)(r0 + row) * DIM + kq * 8);
    }
    // ---- B tile 0 -> buffer 0
#pragma unroll
    for (int i = 0; i < 16; ++i) {
        int u = tid + i * 256;            // 0..4095
        int n = u >> 4, kq = u & 15;
        cp16(sB + (uint32_t)(n * STRB + kq * 16),
             g_repsb + (size_t)n * DIM + kq * 8);
    }
    cp_commit();

    // ldmatrix lane addresses (byte offsets; +ks*32 per k16 step)
    uint32_t aAddr[4];
#pragma unroll
    for (int mt = 0; mt < 4; ++mt)
        aAddr[mt] = sA + (uint32_t)((warpM*64 + mt*16 + (mi & 1)*8 + ri) * STRB
                                    + (mi >> 1) * 16);
    uint32_t bOff[4];
#pragma unroll
    for (int np = 0; np < 4; ++np)
        bOff[np] = (uint32_t)((warpN*64 + np*16 + (mi >> 1)*8 + ri) * STRB
                              + (mi & 1) * 16);

    float C[4][8][4];
#pragma unroll
    for (int mt = 0; mt < 4; ++mt)
#pragma unroll
        for (int nt = 0; nt < 8; ++nt)
#pragma unroll
            for (int e = 0; e < 4; ++e) C[mt][nt][e] = 0.f;

    float Mx[8], Sx[8], thr[8];
#pragma unroll
    for (int s = 0; s < 8; ++s) { Mx[s] = -1e30f; Sx[s] = 0.f; thr[s] = -1e30f; }

    for (int t = 0; t < NT; ++t) {
        const uint32_t bufB = sB + (uint32_t)(t & 1) * B_BYTES;
        cp_wait0();
        __syncthreads();                  // tile t visible; prev compute done

        // prefetch tile t+1 into the other buffer (overlaps compute)
        if (t + 1 < NT) {
            const uint32_t nbB = sB + (uint32_t)((t + 1) & 1) * B_BYTES;
            const int c0n = (t + 1) * BN;
#pragma unroll
            for (int i = 0; i < 16; ++i) {
                int u = tid + i * 256;
                int n = u >> 4, kq = u & 15;
                cp16(nbB + (uint32_t)(n * STRB + kq * 16),
                     g_repsb + (size_t)(c0n + n) * DIM + kq * 8);
            }
        }
        cp_commit();

        // ---- compute: 8 k16 steps
#pragma unroll
        for (int ks = 0; ks < 8; ++ks) {
            uint32_t a[4][4], b[4][4];
#pragma unroll
            for (int mt = 0; mt < 4; ++mt) ldsm4(a[mt], aAddr[mt] + ks * 32);
#pragma unroll
            for (int np = 0; np < 4; ++np) ldsm4(b[np], bufB + bOff[np] + ks * 32);
            // b[np] = {b0(n even), b1(n even), b0(n odd), b1(n odd)}
#pragma unroll
            for (int mt = 0; mt < 4; ++mt)
#pragma unroll
                for (int np = 0; np < 4; ++np) {
                    mma16816(C[mt][np*2],     a[mt], b[np][0], b[np][1]);
                    mma16816(C[mt][np*2 + 1], a[mt], b[np][2], b[np][3]);
                }
        }

        // ---- epilogue: online (M, S, thr) update over this 256-col tile
        const int c0 = t * BN;
#pragma unroll
        for (int s = 0; s < 8; ++s) {
            const int mt = s >> 1, h = s & 1;
            const int grow = r0 + warpM*64 + mt*16 + rt + 8*h;
            float v[16];
            float tmax = -1e30f;
#pragma unroll
            for (int nt = 0; nt < 8; ++nt) {
#pragma unroll
                for (int e = 0; e < 2; ++e) {
                    float sv = C[mt][nt][h*2 + e] * INVT;
                    int col = c0 + warpN*64 + nt*8 + 2*qt + e;
                    if (col == grow) sv = -1e30f;          // mask diagonal
                    v[nt*2 + e] = sv;
                    tmax = fmaxf(tmax, sv);
                }
            }
            if (tmax > Mx[s]) {
                float mo = __expf(Mx[s]);
                float mn = __expf(tmax);
                Sx[s] *= __expf(mo - mn);                  // underflows safely
                Mx[s] = tmax;
                thr[s] = (mn > 26.f) ? __logf(mn - 25.f) : -1e30f;
            }
            if (tmax > thr[s]) {                           // rare after warm-up
                const float eM = __expf(Mx[s]);
#pragma unroll
                for (int j = 0; j < 16; ++j)
                    if (v[j] > thr[s])
                        Sx[s] += __expf(__expf(v[j]) - eM);
            }
        }
#pragma unroll
        for (int mt = 0; mt < 4; ++mt)
#pragma unroll
            for (int nt = 0; nt < 8; ++nt)
#pragma unroll
                for (int e = 0; e < 4; ++e) C[mt][nt][e] = 0.f;
    }

    // ---- combine the 16 partials per row (4 N-warps x 4 lane-cols)
    __syncthreads();
    float* shM = smf;
    float* shS = smf + 2048;
#pragma unroll
    for (int s = 0; s < 8; ++s) {
        const int mt = s >> 1, h = s & 1;
        const int lrow = warpM*64 + mt*16 + rt + 8*h;
        shM[lrow * 16 + warpN * 4 + qt] = Mx[s];
        shS[lrow * 16 + warpN * 4 + qt] = Sx[s];
    }
    __syncthreads();
    if (tid < 128) {
        float bm = -1e30f, bs = 0.f;
#pragma unroll
        for (int t = 0; t < 16; ++t) {
            float Mi = shM[tid * 16 + t];
            float Si = shS[tid * 16 + t];
            if (Mi > bm) {
                bs = bs * __expf(__expf(bm) - __expf(Mi)) + Si;
                bm = Mi;
            } else {
                bs += Si * __expf(__expf(Mi) - __expf(bm));
            }
        }
        g_lse[r0 + tid] = __expf(bm) + logf(bs);   // lse = e_max + log(S)
    }
}

// ---------------------------------------------------------------------------
// Final scalar: mean(lse - pos), fp64 accumulation.
// ---------------------------------------------------------------------------
__global__ void nt_finalize(float* __restrict__ out) {
    __shared__ double red[1024];
    double acc = 0.0;
    for (int i = threadIdx.x; i < NTOT; i += 1024) {
        float pos = g_pos[(i < NB) ? i : (i - NB)];
        acc += (double)g_lse[i] - (double)pos;
    }
    red[threadIdx.x] = acc;
    __syncthreads();
    for (int s = 512; s; s >>= 1) {
        if (threadIdx.x < s) red[threadIdx.x] += red[threadIdx.x + s];
        __syncthreads();
    }
    if (threadIdx.x == 0) out[0] = (float)(red[0] / (double)NTOT);
}

// ---------------------------------------------------------------------------
extern "C" void kernel_launch(void* const* d_in, const int* in_sizes, int n_in,
                              void* d_out, int out_size) {
    const float* zi = (const float*)d_in[0];
    const float* zj = (const float*)d_in[1];
    float* out = (float*)d_out;

    cudaFuncSetAttribute(nt_main, cudaFuncAttributeMaxDynamicSharedMemorySize, SMEM_REQ);

    nt_normalize<<<NTOT / 8, 256>>>(zi, zj);
    nt_pos<<<NB / 8, 256>>>(zi, zj);
    nt_main<<<NTOT / BM, 256, SMEM_REQ>>>();
    nt_finalize<<<1, 1024>>>(out);
}

// round 14
// speedup vs baseline: 1.0152x; 1.0152x over previous
#include <cuda_runtime.h>
#include <cuda_bf16.h>
#include <math.h>
#include <stdint.h>

#define NB    8192
#define DIM   128
#define NTOT  16384
#define INVT  14.285714285714286f

#define BM 128
#define BN 256
#define NT (NTOT/BN)              // 64 N-tiles per CTA

#define STRB 272                  // smem row stride in bytes (128 bf16 + 8 pad)
#define A_BYTES (128*STRB)        // 34816
#define B_BYTES (256*STRB)        // 69632 per buffer
#define SMEM_REQ (A_BYTES + 2*B_BYTES)   // 174080

__device__ __nv_bfloat16 g_repsb[(size_t)NTOT * DIM];   // 4 MB, L2-resident
__device__ float g_lse[NTOT];
__device__ float g_pos[NB];

// ---------------------------------------------------------------------------
__device__ __forceinline__ uint32_t smem_u32(const void* p) {
    uint32_t r;
    asm("{ .reg .u64 t; cvta.to.shared.u64 t, %1; cvt.u32.u64 %0, t; }" : "=r"(r) : "l"(p));
    return r;
}
__device__ __forceinline__ void cp16(uint32_t dst, const void* src) {
    asm volatile("cp.async.cg.shared.global [%0], [%1], 16;" :: "r"(dst), "l"(src));
}
__device__ __forceinline__ void cp_commit() { asm volatile("cp.async.commit_group;"); }
__device__ __forceinline__ void cp_wait0()  { asm volatile("cp.async.wait_group 0;"); }

__device__ __forceinline__ void ldsm4(uint32_t r[4], uint32_t addr) {
    asm volatile("ldmatrix.sync.aligned.m8n8.x4.shared.b16 {%0,%1,%2,%3}, [%4];"
        : "=r"(r[0]), "=r"(r[1]), "=r"(r[2]), "=r"(r[3]) : "r"(addr));
}
__device__ __forceinline__ void mma16816(float c[4], const uint32_t a[4],
                                         uint32_t b0, uint32_t b1) {
    asm volatile(
        "mma.sync.aligned.m16n8k16.row.col.f32.bf16.bf16.f32 "
        "{%0,%1,%2,%3}, {%4,%5,%6,%7}, {%8,%9}, {%0,%1,%2,%3};"
        : "+f"(c[0]), "+f"(c[1]), "+f"(c[2]), "+f"(c[3])
        : "r"(a[0]), "r"(a[1]), "r"(a[2]), "r"(a[3]), "r"(b0), "r"(b1));
}

// ---------------------------------------------------------------------------
// Normalize rows of [z_i; z_j] -> bf16(rn). One warp per row.
// ---------------------------------------------------------------------------
__global__ void nt_normalize(const float* __restrict__ zi,
                             const float* __restrict__ zj) {
    int row  = (blockIdx.x * blockDim.x + threadIdx.x) >> 5;
    int lane = threadIdx.x & 31;
    if (row >= NTOT) return;
    const float* src = (row < NB) ? (zi + (size_t)row * DIM)
                                  : (zj + (size_t)(row - NB) * DIM);
    float4 v = ((const float4*)src)[lane];
    float ss = v.x*v.x + v.y*v.y + v.z*v.z + v.w*v.w;
#pragma unroll
    for (int o = 16; o; o >>= 1) ss += __shfl_xor_sync(0xffffffffu, ss, o);
    float inv = 1.0f / fmaxf(sqrtf(ss), 1e-12f);
    __nv_bfloat162 p0, p1;
    p0.x = __float2bfloat16_rn(v.x*inv); p0.y = __float2bfloat16_rn(v.y*inv);
    p1.x = __float2bfloat16_rn(v.z*inv); p1.y = __float2bfloat16_rn(v.w*inv);
    __nv_bfloat162* dst = (__nv_bfloat162*)(g_repsb + (size_t)row * DIM);
    dst[lane*2]   = p0;
    dst[lane*2+1] = p1;
}

// ---------------------------------------------------------------------------
// pos[i] = exp(dot(zi_i/|zi_i|, zj_i/|zj_i|) / T)   (exact fp32 path)
// ---------------------------------------------------------------------------
__global__ void nt_pos(const float* __restrict__ zi,
                       const float* __restrict__ zj) {
    int row  = (blockIdx.x * blockDim.x + threadIdx.x) >> 5;
    int lane = threadIdx.x & 31;
    if (row >= NB) return;
    float4 a = ((const float4*)(zi + (size_t)row * DIM))[lane];
    float4 b = ((const float4*)(zj + (size_t)row * DIM))[lane];
    float sa = a.x*a.x + a.y*a.y + a.z*a.z + a.w*a.w;
    float sb = b.x*b.x + b.y*b.y + b.z*b.z + b.w*b.w;
    float d  = a.x*b.x + a.y*b.y + a.z*b.z + a.w*b.w;
#pragma unroll
    for (int o = 16; o; o >>= 1) {
        sa += __shfl_xor_sync(0xffffffffu, sa, o);
        sb += __shfl_xor_sync(0xffffffffu, sb, o);
        d  += __shfl_xor_sync(0xffffffffu, d,  o);
    }
    if (lane == 0) {
        float na = fmaxf(sqrtf(sa), 1e-12f);
        float nb = fmaxf(sqrtf(sb), 1e-12f);
        g_pos[row] = expf(d / (na * nb) * INVT);
    }
}

// ---------------------------------------------------------------------------
// Fused bf16 mma.sync GEMM + online double-logsumexp.
// CTA: 128 rows x 64 tiles of 256 cols. 8 warps = 2(M) x 4(N), warp tile 64x64.
// K=128 in one shot per tile (8 k16 steps); B tiles double-buffered (cp.async).
// ---------------------------------------------------------------------------
__global__ void __launch_bounds__(256, 1) nt_main() {
    extern __shared__ char smraw[];
    const uint32_t sA = smem_u32(smraw);
    const uint32_t sB = sA + A_BYTES;
    float* smf = (float*)smraw;

    const int tid   = threadIdx.x;
    const int lane  = tid & 31;
    const int wid   = tid >> 5;
    const int warpM = wid >> 2;       // 0..1
    const int warpN = wid & 3;        // 0..3
    const int mi    = lane >> 3;      // ldmatrix quadrant
    const int ri    = lane & 7;
    const int rt    = lane >> 2;      // C frag row
    const int qt    = lane & 3;       // C frag col pair
    const int r0    = blockIdx.x * BM;

    // ---- A block (128x128 bf16) -> smem
#pragma unroll
    for (int i = 0; i < 8; ++i) {
        int u = tid + i * 256;            // 0..2047
        int row = u >> 4, kq = u & 15;
        cp16(sA + (uint32_t)(row * STRB + kq * 16),
             g_repsb + (size_t)(r0 + row) * DIM + kq * 8);
    }
    // ---- B tile 0 -> buffer 0
#pragma unroll
    for (int i = 0; i < 16; ++i) {
        int u = tid + i * 256;            // 0..4095
        int n = u >> 4, kq = u & 15;
        cp16(sB + (uint32_t)(n * STRB + kq * 16),
             g_repsb + (size_t)n * DIM + kq * 8);
    }
    cp_commit();

    // ldmatrix lane addresses (byte offsets; +ks*32 per k16 step)
    uint32_t aAddr[4];
#pragma unroll
    for (int mt = 0; mt < 4; ++mt)
        aAddr[mt] = sA + (uint32_t)((warpM*64 + mt*16 + (mi & 1)*8 + ri) * STRB
                                    + (mi >> 1) * 16);
    uint32_t bOff[4];
#pragma unroll
    for (int np = 0; np < 4; ++np)
        bOff[np] = (uint32_t)((warpN*64 + np*16 + (mi >> 1)*8 + ri) * STRB
                              + (mi & 1) * 16);

    float C[4][8][4];
#pragma unroll
    for (int mt = 0; mt < 4; ++mt)
#pragma unroll
        for (int nt = 0; nt < 8; ++nt)
#pragma unroll
            for (int e = 0; e < 4; ++e) C[mt][nt][e] = 0.f;

    float Mx[8], Sx[8], thr[8];
#pragma unroll
    for (int s = 0; s < 8; ++s) { Mx[s] = -1e30f; Sx[s] = 0.f; thr[s] = -1e30f; }

    for (int t = 0; t < NT; ++t) {
        const uint32_t bufB = sB + (uint32_t)(t & 1) * B_BYTES;
        cp_wait0();
        __syncthreads();                  // tile t visible; prev compute done

        // prefetch tile t+1 into the other buffer (overlaps compute)
        if (t + 1 < NT) {
            const uint32_t nbB = sB + (uint32_t)((t + 1) & 1) * B_BYTES;
            const int c0n = (t + 1) * BN;
#pragma unroll
            for (int i = 0; i < 16; ++i) {
                int u = tid + i * 256;
                int n = u >> 4, kq = u & 15;
                cp16(nbB + (uint32_t)(n * STRB + kq * 16),
                     g_repsb + (size_t)(c0n + n) * DIM + kq * 8);
            }
        }
        cp_commit();

        // ---- compute: 8 k16 steps
#pragma unroll
        for (int ks = 0; ks < 8; ++ks) {
            uint32_t a[4][4], b[4][4];
#pragma unroll
            for (int mt = 0; mt < 4; ++mt) ldsm4(a[mt], aAddr[mt] + ks * 32);
#pragma unroll
            for (int np = 0; np < 4; ++np) ldsm4(b[np], bufB + bOff[np] + ks * 32);
            // b[np] = {b0(n even), b1(n even), b0(n odd), b1(n odd)}
#pragma unroll
            for (int mt = 0; mt < 4; ++mt)
#pragma unroll
                for (int np = 0; np < 4; ++np) {
                    mma16816(C[mt][np*2],     a[mt], b[np][0], b[np][1]);
                    mma16816(C[mt][np*2 + 1], a[mt], b[np][2], b[np][3]);
                }
        }

        // ---- epilogue: online (M, S, thr) update over this 256-col tile
        const int c0 = t * BN;
#pragma unroll
        for (int s = 0; s < 8; ++s) {
            const int mt = s >> 1, h = s & 1;
            const int grow = r0 + warpM*64 + mt*16 + rt + 8*h;
            float v[16];
            float tmax = -1e30f;
#pragma unroll
            for (int nt = 0; nt < 8; ++nt) {
#pragma unroll
                for (int e = 0; e < 2; ++e) {
                    float sv = C[mt][nt][h*2 + e] * INVT;
                    int col = c0 + warpN*64 + nt*8 + 2*qt + e;
                    if (col == grow) sv = -1e30f;          // mask diagonal
                    v[nt*2 + e] = sv;
                    tmax = fmaxf(tmax, sv);
                }
            }
            if (tmax > Mx[s]) {
                float mo = __expf(Mx[s]);
                float mn = __expf(tmax);
                Sx[s] *= __expf(mo - mn);                  // underflows safely
                Mx[s] = tmax;
                thr[s] = (mn > 26.f) ? __logf(mn - 25.f) : -1e30f;
            }
            if (tmax > thr[s]) {                           // rare after warm-up
                const float eM = __expf(Mx[s]);
#pragma unroll
                for (int j = 0; j < 16; ++j)
                    if (v[j] > thr[s])
                        Sx[s] += __expf(__expf(v[j]) - eM);
            }
        }
#pragma unroll
        for (int mt = 0; mt < 4; ++mt)
#pragma unroll
            for (int nt = 0; nt < 8; ++nt)
#pragma unroll
                for (int e = 0; e < 4; ++e) C[mt][nt][e] = 0.f;
    }

    // ---- combine the 16 partials per row (4 N-warps x 4 lane-cols)
    __syncthreads();
    float* shM = smf;
    float* shS = smf + 2048;
#pragma unroll
    for (int s = 0; s < 8; ++s) {
        const int mt = s >> 1, h = s & 1;
        const int lrow = warpM*64 + mt*16 + rt + 8*h;
        shM[lrow * 16 + warpN * 4 + qt] = Mx[s];
        shS[lrow * 16 + warpN * 4 + qt] = Sx[s];
    }
    __syncthreads();
    if (tid < 128) {
        float bm = -1e30f, bs = 0.f;
#pragma unroll
        for (int t = 0; t < 16; ++t) {
            float Mi = shM[tid * 16 + t];
            float Si = shS[tid * 16 + t];
            if (Mi > bm) {
                bs = bs * __expf(__expf(bm) - __expf(Mi)) + Si;
                bm = Mi;
            } else {
                bs += Si * __expf(__expf(Mi) - __expf(bm));
            }
        }
        g_lse[r0 + tid] = __expf(bm) + logf(bs);   // lse = e_max + log(S)
    }
}

// ---------------------------------------------------------------------------
// Final scalar: mean(lse - pos), fp64 accumulation.
// ---------------------------------------------------------------------------
__global__ void nt_finalize(float* __restrict__ out) {
    __shared__ double red[1024];
    double acc = 0.0;
    for (int i = threadIdx.x; i < NTOT; i += 1024) {
        float pos = g_pos[(i < NB) ? i : (i - NB)];
        acc += (double)g_lse[i] - (double)pos;
    }
    red[threadIdx.x] = acc;
    __syncthreads();
    for (int s = 512; s; s >>= 1) {
        if (threadIdx.x < s) red[threadIdx.x] += red[threadIdx.x + s];
        __syncthreads();
    }
    if (threadIdx.x == 0) out[0] = (float)(red[0] / (double)NTOT);
}

// ---------------------------------------------------------------------------
extern "C" void kernel_launch(void* const* d_in, const int* in_sizes, int n_in,
                              void* d_out, int out_size) {
    const float* zi = (const float*)d_in[0];
    const float* zj = (const float*)d_in[1];
    float* out = (float*)d_out;

    cudaFuncSetAttribute(nt_main, cudaFuncAttributeMaxDynamicSharedMemorySize, SMEM_REQ);

    nt_normalize<<<NTOT / 8, 256>>>(zi, zj);
    nt_pos<<<NB / 8, 256>>>(zi, zj);
    nt_main<<<NTOT / BM, 256, SMEM_REQ>>>();
    nt_finalize<<<1, 1024>>>(out);
}

// round 15
// speedup vs baseline: 1.0172x; 1.0020x over previous
#include <cuda_runtime.h>
#include <cuda_bf16.h>
#include <math.h>
#include <stdint.h>

#define NB    8192
#define DIM   128
#define NTOT  16384
#define INVT  14.285714285714286f

#define BM 128
#define BN 256
#define NT (NTOT/BN)              // 64 N-tiles per CTA

#define STRB 272                  // smem row stride in bytes (128 bf16 + 8 pad)
#define A_BYTES (128*STRB)        // 34816
#define B_BYTES (256*STRB)        // 69632 per buffer
#define SMEM_REQ (A_BYTES + 2*B_BYTES)   // 174080

__device__ __nv_bfloat16 g_repsb[(size_t)NTOT * DIM];   // 4 MB, L2-resident
__device__ float g_lse[NTOT];
__device__ float g_pos[NB];

// ---------------------------------------------------------------------------
__device__ __forceinline__ uint32_t smem_u32(const void* p) {
    uint32_t r;
    asm("{ .reg .u64 t; cvta.to.shared.u64 t, %1; cvt.u32.u64 %0, t; }" : "=r"(r) : "l"(p));
    return r;
}
__device__ __forceinline__ void cp16(uint32_t dst, const void* src) {
    asm volatile("cp.async.cg.shared.global [%0], [%1], 16;" :: "r"(dst), "l"(src));
}
__device__ __forceinline__ void cp_commit() { asm volatile("cp.async.commit_group;"); }
__device__ __forceinline__ void cp_wait0()  { asm volatile("cp.async.wait_group 0;"); }

__device__ __forceinline__ void ldsm4(uint32_t r[4], uint32_t addr) {
    asm volatile("ldmatrix.sync.aligned.m8n8.x4.shared.b16 {%0,%1,%2,%3}, [%4];"
        : "=r"(r[0]), "=r"(r[1]), "=r"(r[2]), "=r"(r[3]) : "r"(addr));
}
__device__ __forceinline__ void mma16816(float c[4], const uint32_t a[4],
                                         uint32_t b0, uint32_t b1) {
    asm volatile(
        "mma.sync.aligned.m16n8k16.row.col.f32.bf16.bf16.f32 "
        "{%0,%1,%2,%3}, {%4,%5,%6,%7}, {%8,%9}, {%0,%1,%2,%3};"
        : "+f"(c[0]), "+f"(c[1]), "+f"(c[2]), "+f"(c[3])
        : "r"(a[0]), "r"(a[1]), "r"(a[2]), "r"(a[3]), "r"(b0), "r"(b1));
}

// ---------------------------------------------------------------------------
// Normalize rows of [z_i; z_j] -> bf16(rn). One warp per row.
// ---------------------------------------------------------------------------
__global__ void nt_normalize(const float* __restrict__ zi,
                             const float* __restrict__ zj) {
    int row  = (blockIdx.x * blockDim.x + threadIdx.x) >> 5;
    int lane = threadIdx.x & 31;
    if (row >= NTOT) return;
    const float* src = (row < NB) ? (zi + (size_t)row * DIM)
                                  : (zj + (size_t)(row - NB) * DIM);
    float4 v = ((const float4*)src)[lane];
    float ss = v.x*v.x + v.y*v.y + v.z*v.z + v.w*v.w;
#pragma unroll
    for (int o = 16; o; o >>= 1) ss += __shfl_xor_sync(0xffffffffu, ss, o);
    float inv = 1.0f / fmaxf(sqrtf(ss), 1e-12f);
    __nv_bfloat162 p0, p1;
    p0.x = __float2bfloat16_rn(v.x*inv); p0.y = __float2bfloat16_rn(v.y*inv);
    p1.x = __float2bfloat16_rn(v.z*inv); p1.y = __float2bfloat16_rn(v.w*inv);
    __nv_bfloat162* dst = (__nv_bfloat162*)(g_repsb + (size_t)row * DIM);
    dst[lane*2]   = p0;
    dst[lane*2+1] = p1;
}

// ---------------------------------------------------------------------------
// pos[i] = exp(dot(zi_i/|zi_i|, zj_i/|zj_i|) / T)   (exact fp32 path)
// ---------------------------------------------------------------------------
__global__ void nt_pos(const float* __restrict__ zi,
                       const float* __restrict__ zj) {
    int row  = (blockIdx.x * blockDim.x + threadIdx.x) >> 5;
    int lane = threadIdx.x & 31;
    if (row >= NB) return;
    float4 a = ((const float4*)(zi + (size_t)row * DIM))[lane];
    float4 b = ((const float4*)(zj + (size_t)row * DIM))[lane];
    float sa = a.x*a.x + a.y*a.y + a.z*a.z + a.w*a.w;
    float sb = b.x*b.x + b.y*b.y + b.z*b.z + b.w*b.w;
    float d  = a.x*b.x + a.y*b.y + a.z*b.z + a.w*b.w;
#pragma unroll
    for (int o = 16; o; o >>= 1) {
        sa += __shfl_xor_sync(0xffffffffu, sa, o);
        sb += __shfl_xor_sync(0xffffffffu, sb, o);
        d  += __shfl_xor_sync(0xffffffffu, d,  o);
    }
    if (lane == 0) {
        float na = fmaxf(sqrtf(sa), 1e-12f);
        float nb = fmaxf(sqrtf(sb), 1e-12f);
        g_pos[row] = expf(d / (na * nb) * INVT);
    }
}

// ---------------------------------------------------------------------------
// Fused bf16 mma.sync GEMM + online double-logsumexp.
// CTA: 128 rows x 64 tiles of 256 cols. 8 warps = 2(M) x 4(N), warp tile 64x64.
// K=128 in one shot per tile (8 k16 steps); B tiles double-buffered (cp.async).
// ---------------------------------------------------------------------------
__global__ void __launch_bounds__(256, 1) nt_main() {
    extern __shared__ char smraw[];
    const uint32_t sA = smem_u32(smraw);
    const uint32_t sB = sA + A_BYTES;
    float* smf = (float*)smraw;

    const int tid   = threadIdx.x;
    const int lane  = tid & 31;
    const int wid   = tid >> 5;
    const int warpM = wid >> 2;       // 0..1
    const int warpN = wid & 3;        // 0..3
    const int mi    = lane >> 3;      // ldmatrix quadrant
    const int ri    = lane & 7;
    const int rt    = lane >> 2;      // C frag row
    const int qt    = lane & 3;       // C frag col pair
    const int r0    = blockIdx.x * BM;

    // ---- A block (128x128 bf16) -> smem
#pragma unroll
    for (int i = 0; i < 8; ++i) {
        int u = tid + i * 256;            // 0..2047
        int row = u >> 4, kq = u & 15;
        cp16(sA + (uint32_t)(row * STRB + kq * 16),
             g_repsb + (size_t)(r0 + row) * DIM + kq * 8);
    }
    // ---- B tile 0 -> buffer 0
#pragma unroll
    for (int i = 0; i < 16; ++i) {
        int u = tid + i * 256;            // 0..4095
        int n = u >> 4, kq = u & 15;
        cp16(sB + (uint32_t)(n * STRB + kq * 16),
             g_repsb + (size_t)n * DIM + kq * 8);
    }
    cp_commit();

    // ldmatrix lane addresses (byte offsets; +ks*32 per k16 step)
    uint32_t aAddr[4];
#pragma unroll
    for (int mt = 0; mt < 4; ++mt)
        aAddr[mt] = sA + (uint32_t)((warpM*64 + mt*16 + (mi & 1)*8 + ri) * STRB
                                    + (mi >> 1) * 16);
    uint32_t bOff[4];
#pragma unroll
    for (int np = 0; np < 4; ++np)
        bOff[np] = (uint32_t)((warpN*64 + np*16 + (mi >> 1)*8 + ri) * STRB
                              + (mi & 1) * 16);

    float C[4][8][4];
#pragma unroll
    for (int mt = 0; mt < 4; ++mt)
#pragma unroll
        for (int nt = 0; nt < 8; ++nt)
#pragma unroll
            for (int e = 0; e < 4; ++e) C[mt][nt][e] = 0.f;

    float Mx[8], Sx[8], thr[8];
#pragma unroll
    for (int s = 0; s < 8; ++s) { Mx[s] = -1e30f; Sx[s] = 0.f; thr[s] = -1e30f; }

    for (int t = 0; t < NT; ++t) {
        const uint32_t bufB = sB + (uint32_t)(t & 1) * B_BYTES;
        cp_wait0();
        __syncthreads();                  // tile t visible; prev compute done

        // prefetch tile t+1 into the other buffer (overlaps compute)
        if (t + 1 < NT) {
            const uint32_t nbB = sB + (uint32_t)((t + 1) & 1) * B_BYTES;
            const int c0n = (t + 1) * BN;
#pragma unroll
            for (int i = 0; i < 16; ++i) {
                int u = tid + i * 256;
                int n = u >> 4, kq = u & 15;
                cp16(nbB + (uint32_t)(n * STRB + kq * 16),
                     g_repsb + (size_t)(c0n + n) * DIM + kq * 8);
            }
        }
        cp_commit();

        // ---- compute: 8 k16 steps
#pragma unroll
        for (int ks = 0; ks < 8; ++ks) {
            uint32_t a[4][4], b[4][4];
#pragma unroll
            for (int mt = 0; mt < 4; ++mt) ldsm4(a[mt], aAddr[mt] + ks * 32);
#pragma unroll
            for (int np = 0; np < 4; ++np) ldsm4(b[np], bufB + bOff[np] + ks * 32);
            // b[np] = {b0(n even), b1(n even), b0(n odd), b1(n odd)}
#pragma unroll
            for (int mt = 0; mt < 4; ++mt)
#pragma unroll
                for (int np = 0; np < 4; ++np) {
                    mma16816(C[mt][np*2],     a[mt], b[np][0], b[np][1]);
                    mma16816(C[mt][np*2 + 1], a[mt], b[np][2], b[np][3]);
                }
        }

        // ---- epilogue: online (M, S, thr) update over this 256-col tile
        const int c0 = t * BN;
#pragma unroll
        for (int s = 0; s < 8; ++s) {
            const int mt = s >> 1, h = s & 1;
            const int grow = r0 + warpM*64 + mt*16 + rt + 8*h;
            float v[16];
            float tmax = -1e30f;
#pragma unroll
            for (int nt = 0; nt < 8; ++nt) {
#pragma unroll
                for (int e = 0; e < 2; ++e) {
                    float sv = C[mt][nt][h*2 + e] * INVT;
                    int col = c0 + warpN*64 + nt*8 + 2*qt + e;
                    if (col == grow) sv = -1e30f;          // mask diagonal
                    v[nt*2 + e] = sv;
                    tmax = fmaxf(tmax, sv);
                }
            }
            if (tmax > Mx[s]) {
                float mo = __expf(Mx[s]);
                float mn = __expf(tmax);
                Sx[s] *= __expf(mo - mn);                  // underflows safely
                Mx[s] = tmax;
                thr[s] = (mn > 26.f) ? __logf(mn - 25.f) : -1e30f;
            }
            if (tmax > thr[s]) {                           // rare after warm-up
                const float eM = __expf(Mx[s]);
#pragma unroll
                for (int j = 0; j < 16; ++j)
                    if (v[j] > thr[s])
                        Sx[s] += __expf(__expf(v[j]) - eM);
            }
        }
#pragma unroll
        for (int mt = 0; mt < 4; ++mt)
#pragma unroll
            for (int nt = 0; nt < 8; ++nt)
#pragma unroll
                for (int e = 0; e < 4; ++e) C[mt][nt][e] = 0.f;
    }

    // ---- combine the 16 partials per row (4 N-warps x 4 lane-cols)
    __syncthreads();
    float* shM = smf;
    float* shS = smf + 2048;
#pragma unroll
    for (int s = 0; s < 8; ++s) {
        const int mt = s >> 1, h = s & 1;
        const int lrow = warpM*64 + mt*16 + rt + 8*h;
        shM[lrow * 16 + warpN * 4 + qt] = Mx[s];
        shS[lrow * 16 + warpN * 4 + qt] = Sx[s];
    }
    __syncthreads();
    if (tid < 128) {
        float bm = -1e30f, bs = 0.f;
#pragma unroll
        for (int t = 0; t < 16; ++t) {
            float Mi = shM[tid * 16 + t];
            float Si = shS[tid * 16 + t];
            if (Mi > bm) {
                bs = bs * __expf(__expf(bm) - __expf(Mi)) + Si;
                bm = Mi;
            } else {
                bs += Si * __expf(__expf(Mi) - __expf(bm));
            }
        }
        g_lse[r0 + tid] = __expf(bm) + logf(bs);   // lse = e_max + log(S)
    }
}

// ---------------------------------------------------------------------------
// Final scalar: mean(lse - pos), fp64 accumulation.
// ---------------------------------------------------------------------------
__global__ void nt_finalize(float* __restrict__ out) {
    __shared__ double red[1024];
    double acc = 0.0;
    for (int i = threadIdx.x; i < NTOT; i += 1024) {
        float pos = g_pos[(i < NB) ? i : (i - NB)];
        acc += (double)g_lse[i] - (double)pos;
    }
    red[threadIdx.x] = acc;
    __syncthreads();
    for (int s = 512; s; s >>= 1) {
        if (threadIdx.x < s) red[threadIdx.x] += red[threadIdx.x + s];
        __syncthreads();
    }
    if (threadIdx.x == 0) out[0] = (float)(red[0] / (double)NTOT);
}

// ---------------------------------------------------------------------------
extern "C" void kernel_launch(void* const* d_in, const int* in_sizes, int n_in,
                              void* d_out, int out_size) {
    const float* zi = (const float*)d_in[0];
    const float* zj = (const float*)d_in[1];
    float* out = (float*)d_out;

    cudaFuncSetAttribute(nt_main, cudaFuncAttributeMaxDynamicSharedMemorySize, SMEM_REQ);

    nt_normalize<<<NTOT / 8, 256>>>(zi, zj);
    nt_pos<<<NB / 8, 256>>>(zi, zj);
    nt_main<<<NTOT / BM, 256, SMEM_REQ>>>();
    nt_finalize<<<1, 1024>>>(out);
}

// round 16
// speedup vs baseline: 1.0177x; 1.0004x over previous
#include <cuda_runtime.h>
#include <cuda_bf16.h>
#include <math.h>
#include <stdint.h>

#define NB    8192
#define DIM   128
#define NTOT  16384
#define INVT  14.285714285714286f

#define BM 128
#define BN 256
#define NT (NTOT/BN)              // 64 N-tiles per CTA

#define STRB 272                  // smem row stride in bytes (128 bf16 + 8 pad)
#define A_BYTES (128*STRB)        // 34816
#define B_BYTES (256*STRB)        // 69632 per buffer
#define SMEM_REQ (A_BYTES + 2*B_BYTES)   // 174080

__device__ __nv_bfloat16 g_repsb[(size_t)NTOT * DIM];   // 4 MB, L2-resident
__device__ float g_lse[NTOT];
__device__ float g_pos[NB];

// ---------------------------------------------------------------------------
__device__ __forceinline__ uint32_t smem_u32(const void* p) {
    uint32_t r;
    asm("{ .reg .u64 t; cvta.to.shared.u64 t, %1; cvt.u32.u64 %0, t; }" : "=r"(r) : "l"(p));
    return r;
}
__device__ __forceinline__ void cp16(uint32_t dst, const void* src) {
    asm volatile("cp.async.cg.shared.global [%0], [%1], 16;" :: "r"(dst), "l"(src));
}
__device__ __forceinline__ void cp_commit() { asm volatile("cp.async.commit_group;"); }
__device__ __forceinline__ void cp_wait0()  { asm volatile("cp.async.wait_group 0;"); }

__device__ __forceinline__ void ldsm4(uint32_t r[4], uint32_t addr) {
    asm volatile("ldmatrix.sync.aligned.m8n8.x4.shared.b16 {%0,%1,%2,%3}, [%4];"
        : "=r"(r[0]), "=r"(r[1]), "=r"(r[2]), "=r"(r[3]) : "r"(addr));
}
__device__ __forceinline__ void mma16816(float c[4], const uint32_t a[4],
                                         uint32_t b0, uint32_t b1) {
    asm volatile(
        "mma.sync.aligned.m16n8k16.row.col.f32.bf16.bf16.f32 "
        "{%0,%1,%2,%3}, {%4,%5,%6,%7}, {%8,%9}, {%0,%1,%2,%3};"
        : "+f"(c[0]), "+f"(c[1]), "+f"(c[2]), "+f"(c[3])
        : "r"(a[0]), "r"(a[1]), "r"(a[2]), "r"(a[3]), "r"(b0), "r"(b1));
}

// ---------------------------------------------------------------------------
// Normalize rows of [z_i; z_j] -> bf16(rn). One warp per row.
// ---------------------------------------------------------------------------
__global__ void nt_normalize(const float* __restrict__ zi,
                             const float* __restrict__ zj) {
    int row  = (blockIdx.x * blockDim.x + threadIdx.x) >> 5;
    int lane = threadIdx.x & 31;
    if (row >= NTOT) return;
    const float* src = (row < NB) ? (zi + (size_t)row * DIM)
                                  : (zj + (size_t)(row - NB) * DIM);
    float4 v = ((const float4*)src)[lane];
    float ss = v.x*v.x + v.y*v.y + v.z*v.z + v.w*v.w;
#pragma unroll
    for (int o = 16; o; o >>= 1) ss += __shfl_xor_sync(0xffffffffu, ss, o);
    float inv = 1.0f / fmaxf(sqrtf(ss), 1e-12f);
    __nv_bfloat162 p0, p1;
    p0.x = __float2bfloat16_rn(v.x*inv); p0.y = __float2bfloat16_rn(v.y*inv);
    p1.x = __float2bfloat16_rn(v.z*inv); p1.y = __float2bfloat16_rn(v.w*inv);
    __nv_bfloat162* dst = (__nv_bfloat162*)(g_repsb + (size_t)row * DIM);
    dst[lane*2]   = p0;
    dst[lane*2+1] = p1;
}

// ---------------------------------------------------------------------------
// pos[i] = exp(dot(zi_i/|zi_i|, zj_i/|zj_i|) / T)   (exact fp32 path)
// ---------------------------------------------------------------------------
__global__ void nt_pos(const float* __restrict__ zi,
                       const float* __restrict__ zj) {
    int row  = (blockIdx.x * blockDim.x + threadIdx.x) >> 5;
    int lane = threadIdx.x & 31;
    if (row >= NB) return;
    float4 a = ((const float4*)(zi + (size_t)row * DIM))[lane];
    float4 b = ((const float4*)(zj + (size_t)row * DIM))[lane];
    float sa = a.x*a.x + a.y*a.y + a.z*a.z + a.w*a.w;
    float sb = b.x*b.x + b.y*b.y + b.z*b.z + b.w*b.w;
    float d  = a.x*b.x + a.y*b.y + a.z*b.z + a.w*b.w;
#pragma unroll
    for (int o = 16; o; o >>= 1) {
        sa += __shfl_xor_sync(0xffffffffu, sa, o);
        sb += __shfl_xor_sync(0xffffffffu, sb, o);
        d  += __shfl_xor_sync(0xffffffffu, d,  o);
    }
    if (lane == 0) {
        float na = fmaxf(sqrtf(sa), 1e-12f);
        float nb = fmaxf(sqrtf(sb), 1e-12f);
        g_pos[row] = expf(d / (na * nb) * INVT);
    }
}

// ---------------------------------------------------------------------------
// Fused bf16 mma.sync GEMM + online double-logsumexp.
// CTA: 128 rows x 64 tiles of 256 cols. 8 warps = 2(M) x 4(N), warp tile 64x64.
// K=128 in one shot per tile (8 k16 steps); B tiles double-buffered (cp.async).
// ---------------------------------------------------------------------------
__global__ void __launch_bounds__(256, 1) nt_main() {
    extern __shared__ char smraw[];
    const uint32_t sA = smem_u32(smraw);
    const uint32_t sB = sA + A_BYTES;
    float* smf = (float*)smraw;

    const int tid   = threadIdx.x;
    const int lane  = tid & 31;
    const int wid   = tid >> 5;
    const int warpM = wid >> 2;       // 0..1
    const int warpN = wid & 3;        // 0..3
    const int mi    = lane >> 3;      // ldmatrix quadrant
    const int ri    = lane & 7;
    const int rt    = lane >> 2;      // C frag row
    const int qt    = lane & 3;       // C frag col pair
    const int r0    = blockIdx.x * BM;

    // ---- A block (128x128 bf16) -> smem
#pragma unroll
    for (int i = 0; i < 8; ++i) {
        int u = tid + i * 256;            // 0..2047
        int row = u >> 4, kq = u & 15;
        cp16(sA + (uint32_t)(row * STRB + kq * 16),
             g_repsb + (size_t)(r0 + row) * DIM + kq * 8);
    }
    // ---- B tile 0 -> buffer 0
#pragma unroll
    for (int i = 0; i < 16; ++i) {
        int u = tid + i * 256;            // 0..4095
        int n = u >> 4, kq = u & 15;
        cp16(sB + (uint32_t)(n * STRB + kq * 16),
             g_repsb + (size_t)n * DIM + kq * 8);
    }
    cp_commit();

    // ldmatrix lane addresses (byte offsets; +ks*32 per k16 step)
    uint32_t aAddr[4];
#pragma unroll
    for (int mt = 0; mt < 4; ++mt)
        aAddr[mt] = sA + (uint32_t)((warpM*64 + mt*16 + (mi & 1)*8 + ri) * STRB
                                    + (mi >> 1) * 16);
    uint32_t bOff[4];
#pragma unroll
    for (int np = 0; np < 4; ++np)
        bOff[np] = (uint32_t)((warpN*64 + np*16 + (mi >> 1)*8 + ri) * STRB
                              + (mi & 1) * 16);

    float C[4][8][4];
#pragma unroll
    for (int mt = 0; mt < 4; ++mt)
#pragma unroll
        for (int nt = 0; nt < 8; ++nt)
#pragma unroll
            for (int e = 0; e < 4; ++e) C[mt][nt][e] = 0.f;

    float Mx[8], Sx[8], thr[8];
#pragma unroll
    for (int s = 0; s < 8; ++s) { Mx[s] = -1e30f; Sx[s] = 0.f; thr[s] = -1e30f; }

    for (int t = 0; t < NT; ++t) {
        const uint32_t bufB = sB + (uint32_t)(t & 1) * B_BYTES;
        cp_wait0();
        __syncthreads();                  // tile t visible; prev compute done

        // prefetch tile t+1 into the other buffer (overlaps compute)
        if (t + 1 < NT) {
            const uint32_t nbB = sB + (uint32_t)((t + 1) & 1) * B_BYTES;
            const int c0n = (t + 1) * BN;
#pragma unroll
            for (int i = 0; i < 16; ++i) {
                int u = tid + i * 256;
                int n = u >> 4, kq = u & 15;
                cp16(nbB + (uint32_t)(n * STRB + kq * 16),
                     g_repsb + (size_t)(c0n + n) * DIM + kq * 8);
            }
        }
        cp_commit();

        // ---- compute: 8 k16 steps
#pragma unroll
        for (int ks = 0; ks < 8; ++ks) {
            uint32_t a[4][4], b[4][4];
#pragma unroll
            for (int mt = 0; mt < 4; ++mt) ldsm4(a[mt], aAddr[mt] + ks * 32);
#pragma unroll
            for (int np = 0; np < 4; ++np) ldsm4(b[np], bufB + bOff[np] + ks * 32);
            // b[np] = {b0(n even), b1(n even), b0(n odd), b1(n odd)}
#pragma unroll
            for (int mt = 0; mt < 4; ++mt)
#pragma unroll
                for (int np = 0; np < 4; ++np) {
                    mma16816(C[mt][np*2],     a[mt], b[np][0], b[np][1]);
                    mma16816(C[mt][np*2 + 1], a[mt], b[np][2], b[np][3]);
                }
        }

        // ---- epilogue: online (M, S, thr) update over this 256-col tile
        const int c0 = t * BN;
#pragma unroll
        for (int s = 0; s < 8; ++s) {
            const int mt = s >> 1, h = s & 1;
            const int grow = r0 + warpM*64 + mt*16 + rt + 8*h;
            float v[16];
            float tmax = -1e30f;
#pragma unroll
            for (int nt = 0; nt < 8; ++nt) {
#pragma unroll
                for (int e = 0; e < 2; ++e) {
                    float sv = C[mt][nt][h*2 + e] * INVT;
                    int col = c0 + warpN*64 + nt*8 + 2*qt + e;
                    if (col == grow) sv = -1e30f;          // mask diagonal
                    v[nt*2 + e] = sv;
                    tmax = fmaxf(tmax, sv);
                }
            }
            if (tmax > Mx[s]) {
                float mo = __expf(Mx[s]);
                float mn = __expf(tmax);
                Sx[s] *= __expf(mo - mn);                  // underflows safely
                Mx[s] = tmax;
                thr[s] = (mn > 26.f) ? __logf(mn - 25.f) : -1e30f;
            }
            if (tmax > thr[s]) {                           // rare after warm-up
                const float eM = __expf(Mx[s]);
#pragma unroll
                for (int j = 0; j < 16; ++j)
                    if (v[j] > thr[s])
                        Sx[s] += __expf(__expf(v[j]) - eM);
            }
        }
#pragma unroll
        for (int mt = 0; mt < 4; ++mt)
#pragma unroll
            for (int nt = 0; nt < 8; ++nt)
#pragma unroll
                for (int e = 0; e < 4; ++e) C[mt][nt][e] = 0.f;
    }

    // ---- combine the 16 partials per row (4 N-warps x 4 lane-cols)
    __syncthreads();
    float* shM = smf;
    float* shS = smf + 2048;
#pragma unroll
    for (int s = 0; s < 8; ++s) {
        const int mt = s >> 1, h = s & 1;
        const int lrow = warpM*64 + mt*16 + rt + 8*h;
        shM[lrow * 16 + warpN * 4 + qt] = Mx[s];
        shS[lrow * 16 + warpN * 4 + qt] = Sx[s];
    }
    __syncthreads();
    if (tid < 128) {
        float bm = -1e30f, bs = 0.f;
#pragma unroll
        for (int t = 0; t < 16; ++t) {
            float Mi = shM[tid * 16 + t];
            float Si = shS[tid * 16 + t];
            if (Mi > bm) {
                bs = bs * __expf(__expf(bm) - __expf(Mi)) + Si;
                bm = Mi;
            } else {
                bs += Si * __expf(__expf(Mi) - __expf(bm));
            }
        }
        g_lse[r0 + tid] = __expf(bm) + logf(bs);   // lse = e_max + log(S)
    }
}

// ---------------------------------------------------------------------------
// Final scalar: mean(lse - pos), fp64 accumulation.
// ---------------------------------------------------------------------------
__global__ void nt_finalize(float* __restrict__ out) {
    __shared__ double red[1024];
    double acc = 0.0;
    for (int i = threadIdx.x; i < NTOT; i += 1024) {
        float pos = g_pos[(i < NB) ? i : (i - NB)];
        acc += (double)g_lse[i] - (double)pos;
    }
    red[threadIdx.x] = acc;
    __syncthreads();
    for (int s = 512; s; s >>= 1) {
        if (threadIdx.x < s) red[threadIdx.x] += red[threadIdx.x + s];
        __syncthreads();
    }
    if (threadIdx.x == 0) out[0] = (float)(red[0] / (double)NTOT);
}

// ---------------------------------------------------------------------------
extern "C" void kernel_launch(void* const* d_in, const int* in_sizes, int n_in,
                              void* d_out, int out_size) {
    const float* zi = (const float*)d_in[0];
    const float* zj = (const float*)d_in[1];
    float* out = (float*)d_out;

    cudaFuncSetAttribute(nt_main, cudaFuncAttributeMaxDynamicSharedMemorySize, SMEM_REQ);

    nt_normalize<<<NTOT / 8, 256>>>(zi, zj);
    nt_pos<<<NB / 8, 256>>>(zi, zj);
    nt_main<<<NTOT / BM, 256, SMEM_REQ>>>();
    nt_finalize<<<1, 1024>>>(out);
}

// round 17
// speedup vs baseline: 1.0184x; 1.0007x over previous
#include <cuda_runtime.h>
#include <cuda_bf16.h>
#include <math.h>
#include <stdint.h>

#define NB    8192
#define DIM   128
#define NTOT  16384
#define INVT  14.285714285714286f

#define BM 128
#define BN 256
#define NT (NTOT/BN)              // 64 N-tiles per CTA

#define STRB 272                  // smem row stride in bytes (128 bf16 + 8 pad)
#define A_BYTES (128*STRB)        // 34816
#define B_BYTES (256*STRB)        // 69632 per buffer
#define SMEM_REQ (A_BYTES + 2*B_BYTES)   // 174080

__device__ __nv_bfloat16 g_repsb[(size_t)NTOT * DIM];   // 4 MB, L2-resident
__device__ float g_lse[NTOT];
__device__ float g_pos[NB];

// ---------------------------------------------------------------------------
__device__ __forceinline__ uint32_t smem_u32(const void* p) {
    uint32_t r;
    asm("{ .reg .u64 t; cvta.to.shared.u64 t, %1; cvt.u32.u64 %0, t; }" : "=r"(r) : "l"(p));
    return r;
}
__device__ __forceinline__ void cp16(uint32_t dst, const void* src) {
    asm volatile("cp.async.cg.shared.global [%0], [%1], 16;" :: "r"(dst), "l"(src));
}
__device__ __forceinline__ void cp_commit() { asm volatile("cp.async.commit_group;"); }
__device__ __forceinline__ void cp_wait0()  { asm volatile("cp.async.wait_group 0;"); }

__device__ __forceinline__ void ldsm4(uint32_t r[4], uint32_t addr) {
    asm volatile("ldmatrix.sync.aligned.m8n8.x4.shared.b16 {%0,%1,%2,%3}, [%4];"
        : "=r"(r[0]), "=r"(r[1]), "=r"(r[2]), "=r"(r[3]) : "r"(addr));
}
__device__ __forceinline__ void mma16816(float c[4], const uint32_t a[4],
                                         uint32_t b0, uint32_t b1) {
    asm volatile(
        "mma.sync.aligned.m16n8k16.row.col.f32.bf16.bf16.f32 "
        "{%0,%1,%2,%3}, {%4,%5,%6,%7}, {%8,%9}, {%0,%1,%2,%3};"
        : "+f"(c[0]), "+f"(c[1]), "+f"(c[2]), "+f"(c[3])
        : "r"(a[0]), "r"(a[1]), "r"(a[2]), "r"(a[3]), "r"(b0), "r"(b1));
}

// ---------------------------------------------------------------------------
// Normalize rows of [z_i; z_j] -> bf16(rn). One warp per row.
// ---------------------------------------------------------------------------
__global__ void nt_normalize(const float* __restrict__ zi,
                             const float* __restrict__ zj) {
    int row  = (blockIdx.x * blockDim.x + threadIdx.x) >> 5;
    int lane = threadIdx.x & 31;
    if (row >= NTOT) return;
    const float* src = (row < NB) ? (zi + (size_t)row * DIM)
                                  : (zj + (size_t)(row - NB) * DIM);
    float4 v = ((const float4*)src)[lane];
    float ss = v.x*v.x + v.y*v.y + v.z*v.z + v.w*v.w;
#pragma unroll
    for (int o = 16; o; o >>= 1) ss += __shfl_xor_sync(0xffffffffu, ss, o);
    float inv = 1.0f / fmaxf(sqrtf(ss), 1e-12f);
    __nv_bfloat162 p0, p1;
    p0.x = __float2bfloat16_rn(v.x*inv); p0.y = __float2bfloat16_rn(v.y*inv);
    p1.x = __float2bfloat16_rn(v.z*inv); p1.y = __float2bfloat16_rn(v.w*inv);
    __nv_bfloat162* dst = (__nv_bfloat162*)(g_repsb + (size_t)row * DIM);
    dst[lane*2]   = p0;
    dst[lane*2+1] = p1;
}

// ---------------------------------------------------------------------------
// pos[i] = exp(dot(zi_i/|zi_i|, zj_i/|zj_i|) / T)   (exact fp32 path)
// ---------------------------------------------------------------------------
__global__ void nt_pos(const float* __restrict__ zi,
                       const float* __restrict__ zj) {
    int row  = (blockIdx.x * blockDim.x + threadIdx.x) >> 5;
    int lane = threadIdx.x & 31;
    if (row >= NB) return;
    float4 a = ((const float4*)(zi + (size_t)row * DIM))[lane];
    float4 b = ((const float4*)(zj + (size_t)row * DIM))[lane];
    float sa = a.x*a.x + a.y*a.y + a.z*a.z + a.w*a.w;
    float sb = b.x*b.x + b.y*b.y + b.z*b.z + b.w*b.w;
    float d  = a.x*b.x + a.y*b.y + a.z*b.z + a.w*b.w;
#pragma unroll
    for (int o = 16; o; o >>= 1) {
        sa += __shfl_xor_sync(0xffffffffu, sa, o);
        sb += __shfl_xor_sync(0xffffffffu, sb, o);
        d  += __shfl_xor_sync(0xffffffffu, d,  o);
    }
    if (lane == 0) {
        float na = fmaxf(sqrtf(sa), 1e-12f);
        float nb = fmaxf(sqrtf(sb), 1e-12f);
        g_pos[row] = expf(d / (na * nb) * INVT);
    }
}

// ---------------------------------------------------------------------------
// Fused bf16 mma.sync GEMM + online double-logsumexp.
// CTA: 128 rows x 64 tiles of 256 cols. 8 warps = 2(M) x 4(N), warp tile 64x64.
// K=128 in one shot per tile (8 k16 steps); B tiles double-buffered (cp.async).
// ---------------------------------------------------------------------------
__global__ void __launch_bounds__(256, 1) nt_main() {
    extern __shared__ char smraw[];
    const uint32_t sA = smem_u32(smraw);
    const uint32_t sB = sA + A_BYTES;
    float* smf = (float*)smraw;

    const int tid   = threadIdx.x;
    const int lane  = tid & 31;
    const int wid   = tid >> 5;
    const int warpM = wid >> 2;       // 0..1
    const int warpN = wid & 3;        // 0..3
    const int mi    = lane >> 3;      // ldmatrix quadrant
    const int ri    = lane & 7;
    const int rt    = lane >> 2;      // C frag row
    const int qt    = lane & 3;       // C frag col pair
    const int r0    = blockIdx.x * BM;

    // ---- A block (128x128 bf16) -> smem
#pragma unroll
    for (int i = 0; i < 8; ++i) {
        int u = tid + i * 256;            // 0..2047
        int row = u >> 4, kq = u & 15;
        cp16(sA + (uint32_t)(row * STRB + kq * 16),
             g_repsb + (size_t)(r0 + row) * DIM + kq * 8);
    }
    // ---- B tile 0 -> buffer 0
#pragma unroll
    for (int i = 0; i < 16; ++i) {
        int u = tid + i * 256;            // 0..4095
        int n = u >> 4, kq = u & 15;
        cp16(sB + (uint32_t)(n * STRB + kq * 16),
             g_repsb + (size_t)n * DIM + kq * 8);
    }
    cp_commit();

    // ldmatrix lane addresses (byte offsets; +ks*32 per k16 step)
    uint32_t aAddr[4];
#pragma unroll
    for (int mt = 0; mt < 4; ++mt)
        aAddr[mt] = sA + (uint32_t)((warpM*64 + mt*16 + (mi & 1)*8 + ri) * STRB
                                    + (mi >> 1) * 16);
    uint32_t bOff[4];
#pragma unroll
    for (int np = 0; np < 4; ++np)
        bOff[np] = (uint32_t)((warpN*64 + np*16 + (mi >> 1)*8 + ri) * STRB
                              + (mi & 1) * 16);

    float C[4][8][4];
#pragma unroll
    for (int mt = 0; mt < 4; ++mt)
#pragma unroll
        for (int nt = 0; nt < 8; ++nt)
#pragma unroll
            for (int e = 0; e < 4; ++e) C[mt][nt][e] = 0.f;

    float Mx[8], Sx[8], thr[8];
#pragma unroll
    for (int s = 0; s < 8; ++s) { Mx[s] = -1e30f; Sx[s] = 0.f; thr[s] = -1e30f; }

    for (int t = 0; t < NT; ++t) {
        const uint32_t bufB = sB + (uint32_t)(t & 1) * B_BYTES;
        cp_wait0();
        __syncthreads();                  // tile t visible; prev compute done

        // prefetch tile t+1 into the other buffer (overlaps compute)
        if (t + 1 < NT) {
            const uint32_t nbB = sB + (uint32_t)((t + 1) & 1) * B_BYTES;
            const int c0n = (t + 1) * BN;
#pragma unroll
            for (int i = 0; i < 16; ++i) {
                int u = tid + i * 256;
                int n = u >> 4, kq = u & 15;
                cp16(nbB + (uint32_t)(n * STRB + kq * 16),
                     g_repsb + (size_t)(c0n + n) * DIM + kq * 8);
            }
        }
        cp_commit();

        // ---- compute: 8 k16 steps
#pragma unroll
        for (int ks = 0; ks < 8; ++ks) {
            uint32_t a[4][4], b[4][4];
#pragma unroll
            for (int mt = 0; mt < 4; ++mt) ldsm4(a[mt], aAddr[mt] + ks * 32);
#pragma unroll
            for (int np = 0; np < 4; ++np) ldsm4(b[np], bufB + bOff[np] + ks * 32);
            // b[np] = {b0(n even), b1(n even), b0(n odd), b1(n odd)}
#pragma unroll
            for (int mt = 0; mt < 4; ++mt)
#pragma unroll
                for (int np = 0; np < 4; ++np) {
                    mma16816(C[mt][np*2],     a[mt], b[np][0], b[np][1]);
                    mma16816(C[mt][np*2 + 1], a[mt], b[np][2], b[np][3]);
                }
        }

        // ---- epilogue: online (M, S, thr) update over this 256-col tile
        const int c0 = t * BN;
#pragma unroll
        for (int s = 0; s < 8; ++s) {
            const int mt = s >> 1, h = s & 1;
            const int grow = r0 + warpM*64 + mt*16 + rt + 8*h;
            float v[16];
            float tmax = -1e30f;
#pragma unroll
            for (int nt = 0; nt < 8; ++nt) {
#pragma unroll
                for (int e = 0; e < 2; ++e) {
                    float sv = C[mt][nt][h*2 + e] * INVT;
                    int col = c0 + warpN*64 + nt*8 + 2*qt + e;
                    if (col == grow) sv = -1e30f;          // mask diagonal
                    v[nt*2 + e] = sv;
                    tmax = fmaxf(tmax, sv);
                }
            }
            if (tmax > Mx[s]) {
                float mo = __expf(Mx[s]);
                float mn = __expf(tmax);
                Sx[s] *= __expf(mo - mn);                  // underflows safely
                Mx[s] = tmax;
                thr[s] = (mn > 26.f) ? __logf(mn - 25.f) : -1e30f;
            }
            if (tmax > thr[s]) {                           // rare after warm-up
                const float eM = __expf(Mx[s]);
#pragma unroll
                for (int j = 0; j < 16; ++j)
                    if (v[j] > thr[s])
                        Sx[s] += __expf(__expf(v[j]) - eM);
            }
        }
#pragma unroll
        for (int mt = 0; mt < 4; ++mt)
#pragma unroll
            for (int nt = 0; nt < 8; ++nt)
#pragma unroll
                for (int e = 0; e < 4; ++e) C[mt][nt][e] = 0.f;
    }

    // ---- combine the 16 partials per row (4 N-warps x 4 lane-cols)
    __syncthreads();
    float* shM = smf;
    float* shS = smf + 2048;
#pragma unroll
    for (int s = 0; s < 8; ++s) {
        const int mt = s >> 1, h = s & 1;
        const int lrow = warpM*64 + mt*16 + rt + 8*h;
        shM[lrow * 16 + warpN * 4 + qt] = Mx[s];
        shS[lrow * 16 + warpN * 4 + qt] = Sx[s];
    }
    __syncthreads();
    if (tid < 128) {
        float bm = -1e30f, bs = 0.f;
#pragma unroll
        for (int t = 0; t < 16; ++t) {
            float Mi = shM[tid * 16 + t];
            float Si = shS[tid * 16 + t];
            if (Mi > bm) {
                bs = bs * __expf(__expf(bm) - __expf(Mi)) + Si;
                bm = Mi;
            } else {
                bs += Si * __expf(__expf(Mi) - __expf(bm));
            }
        }
        g_lse[r0 + tid] = __expf(bm) + logf(bs);   // lse = e_max + log(S)
    }
}

// ---------------------------------------------------------------------------
// Final scalar: mean(lse - pos), fp64 accumulation.
// ---------------------------------------------------------------------------
__global__ void nt_finalize(float* __restrict__ out) {
    __shared__ double red[1024];
    double acc = 0.0;
    for (int i = threadIdx.x; i < NTOT; i += 1024) {
        float pos = g_pos[(i < NB) ? i : (i - NB)];
        acc += (double)g_lse[i] - (double)pos;
    }
    red[threadIdx.x] = acc;
    __syncthreads();
    for (int s = 512; s; s >>= 1) {
        if (threadIdx.x < s) red[threadIdx.x] += red[threadIdx.x + s];
        __syncthreads();
    }
    if (threadIdx.x == 0) out[0] = (float)(red[0] / (double)NTOT);
}

// ---------------------------------------------------------------------------
extern "C" void kernel_launch(void* const* d_in, const int* in_sizes, int n_in,
                              void* d_out, int out_size) {
    const float* zi = (const float*)d_in[0];
    const float* zj = (const float*)d_in[1];
    float* out = (float*)d_out;

    cudaFuncSetAttribute(nt_main, cudaFuncAttributeMaxDynamicSharedMemorySize, SMEM_REQ);

    nt_normalize<<<NTOT / 8, 256>>>(zi, zj);
    nt_pos<<<NB / 8, 256>>>(zi, zj);
    nt_main<<<NTOT / BM, 256, SMEM_REQ>>>();
    nt_finalize<<<1, 1024>>>(out);
}